// round 9
// baseline (speedup 1.0000x reference)
#include <cuda_runtime.h>
#include <cuda_bf16.h>

#define DEV_INLINE __device__ __forceinline__
constexpr int BATCH = 4;

// ---------------- buffer layout (floats) ----------------------------------
// NCHW padded: rows S+2, row-stride S+4. NHWC padded: [B][S+2][S+2][CST].
constexpr int OFF_X    = 0;                         // [4][3][34][36]
constexpr int SZ_X     = BATCH * 3 * 34 * 36;
constexpr int OFF_32A  = OFF_X + SZ_X;              // cap 64
constexpr int SZ_32    = BATCH * 64 * 34 * 36;
constexpr int OFF_32B  = OFF_32A + SZ_32;
constexpr int OFF_16A  = OFF_32B + SZ_32;           // cap 128
constexpr int SZ_16    = BATCH * 128 * 18 * 20;
constexpr int OFF_16B  = OFF_16A + SZ_16;
constexpr int OFF_8A   = OFF_16B + SZ_16;           // NHWC [4][10][10][256]
constexpr int SZ_8     = BATCH * 10 * 10 * 256;
constexpr int OFF_8B   = OFF_8A + SZ_8;
constexpr int OFF_4A   = OFF_8B + SZ_8;             // NHWC [4][6][6][512]
constexpr int SZ_4     = BATCH * 6 * 6 * 512;
constexpr int OFF_4B   = OFF_4A + SZ_4;
constexpr int OFF_2A   = OFF_4B + SZ_4;             // NHWC [4][4][4][512]
constexpr int SZ_2     = BATCH * 4 * 4 * 512;
constexpr int OFF_2B   = OFF_2A + SZ_2;
constexpr int OFF_FCS0 = OFF_2B + SZ_2;             // [4][4096]
constexpr int OFF_FCS1 = OFF_FCS0 + BATCH * 4096;

constexpr int M0  = OFF_FCS1 + BATCH * 4096;
constexpr int M1  = M0  + BATCH * 64  * 32 * 32;
constexpr int M2  = M1  + BATCH * 64  * 32 * 32;
constexpr int M3  = M2  + BATCH * 128 * 16 * 16;
constexpr int M4  = M3  + BATCH * 128 * 16 * 16;
constexpr int M5  = M4  + BATCH * 256 * 8 * 8;
constexpr int M6  = M5  + BATCH * 256 * 8 * 8;
constexpr int M7  = M6  + BATCH * 256 * 8 * 8;
constexpr int M8  = M7  + BATCH * 512 * 4 * 4;
constexpr int M9  = M8  + BATCH * 512 * 4 * 4;
constexpr int M10 = M9  + BATCH * 512 * 4 * 4;
constexpr int M11 = M10 + BATCH * 512 * 2 * 2;
constexpr int M12 = M11 + BATCH * 512 * 2 * 2;
constexpr int MF0 = M12 + BATCH * 512 * 2 * 2;
constexpr int MF1 = MF0 + BATCH * 4096;
constexpr int TOTAL_BUF = MF1 + BATCH * 4096;

__device__ __align__(16) float g_buf[TOTAL_BUF];

// transposed weights [co][tap][ci] for conv layers 4..12
constexpr long WT4  = 0;
constexpr long WT5  = WT4  + 256L * 128 * 9;
constexpr long WT6  = WT5  + 256L * 256 * 9;
constexpr long WT7  = WT6  + 256L * 256 * 9;
constexpr long WT8  = WT7  + 512L * 256 * 9;
constexpr long WT9  = WT8  + 512L * 512 * 9;
constexpr long WT10 = WT9  + 512L * 512 * 9;
constexpr long WT11 = WT10 + 512L * 512 * 9;
constexpr long WT12 = WT11 + 512L * 512 * 9;
constexpr long WT_TOTAL = WT12 + 512L * 512 * 9;
__device__ __align__(16) float g_wt[WT_TOTAL];

// ---------------- multi-compartment LIF (K=2), exact ----------------------
DEV_INLINE float lif_fire(float* memp, float syn, float thr, float leak) {
    float m = leak * (*memp) + syn;
    float e0 = m / thr          - 1.0f;
    float o0 = 1.0f - m / (2.0f * thr);
    float e1 = m / (2.0f * thr) - 1.0f;
    float o1 = 1.0f - m / (4.0f * thr);
    float v = 0.0f;
    if (e0 > 0.0f && o0 >= 0.0f) v = 1.0f;
    if (e1 > 0.0f && o1 >= 0.0f) v = 2.0f;
    *memp = m - thr * v;
    return v;
}

// ---------------- housekeeping --------------------------------------------
__global__ void k_zero(float* __restrict__ dout) {
    int i = blockIdx.x * blockDim.x + threadIdx.x;
    if (i < TOTAL_BUF) g_buf[i] = 0.0f;
    if (i < BATCH * 10) dout[i] = 0.0f;
}

__global__ void k_pad_x(const float* __restrict__ x) {
    int idx = blockIdx.x * blockDim.x + threadIdx.x;
    if (idx >= BATCH * 3 * 32 * 32) return;
    int xx = idx & 31;
    int y  = (idx >> 5) & 31;
    int c  = (idx >> 10) % 3;
    int b  = idx / (3 * 1024);
    g_buf[OFF_X + ((b * 3 + c) * 34 + (y + 1)) * 36 + (xx + 1)] = x[idx];
}

struct WP { const float* p[9]; };
__global__ void k_wtrans_all(WP wp) {
    __shared__ float s[4608];
    const int CINs[9]  = {128, 256, 256, 256, 512, 512, 512, 512, 512};
    const int COUTs[9] = {256, 256, 256, 512, 512, 512, 512, 512, 512};
    const long OFFs[9] = {WT4, WT5, WT6, WT7, WT8, WT9, WT10, WT11, WT12};
    int l  = blockIdx.y;
    int co = blockIdx.x;
    int CIN = CINs[l];
    if (co >= COUTs[l]) return;
    const float* src = wp.p[l] + (long)co * CIN * 9;
    float* dst = g_wt + OFFs[l] + (long)co * CIN * 9;
    int n = CIN * 9;
    for (int i = threadIdx.x; i < n; i += 256) s[i] = src[i];
    __syncthreads();
    for (int i = threadIdx.x; i < n; i += 256) {
        int ci = i % CIN, t = i / CIN;
        dst[i] = s[ci * 9 + t];
    }
}

// ---------------- conv flavor T: NCHW, block per (co,part), smem weights --
template<int CIN, int CICAP, int S, int COUT, int PARTS, int TX>
__global__ __launch_bounds__(256)
void k_conv_T(int in_off, const float* __restrict__ w, int mem_off, int out_off,
              const float* __restrict__ thrp, const float* __restrict__ leakp) {
    constexpr int RS = S + 4, ROWS = S + 2, NX = S / TX;
    constexpr int PLANE = ROWS * RS;
    constexpr int P = BATCH * S * NX;
    constexpr int TPJ = P / PARTS;
    static_assert(TPJ == 256, "block must exactly cover its partition");
    __shared__ __align__(16) float sw[CIN * 12];
    int co   = blockIdx.x / PARTS;
    int part = blockIdx.x % PARTS;
    for (int i = threadIdx.x; i < CIN * 9; i += 256)
        sw[(i / 9) * 12 + (i % 9)] = __ldg(w + (long)co * CIN * 9 + i);
    __syncthreads();

    int tid = part * TPJ + threadIdx.x;
    int x0 = (tid % NX) * TX;
    int y  = (tid / NX) % S;
    int b  = tid / (NX * S);

    const float* ip = g_buf + in_off + (long)b * CICAP * PLANE + y * RS + x0;
    float accA[TX], accB[TX];
#pragma unroll
    for (int t = 0; t < TX; t++) { accA[t] = 0.f; accB[t] = 0.f; }

    for (int ci = 0; ci < CIN; ci++) {
        const float* p = ip + ci * PLANE;
        float r[3][TX + 2];
#pragma unroll
        for (int rr = 0; rr < 3; rr++) {
            if constexpr (TX == 4) {
                float4 a = __ldg((const float4*)(p + rr * RS));
                float4 c = __ldg((const float4*)(p + rr * RS + 4));
                r[rr][0] = a.x; r[rr][1] = a.y; r[rr][2] = a.z; r[rr][3] = a.w;
                r[rr][4] = c.x; r[rr][5] = c.y;
            } else {
                float2 a = __ldg((const float2*)(p + rr * RS));
                float2 c = __ldg((const float2*)(p + rr * RS + 2));
                r[rr][0] = a.x; r[rr][1] = a.y; r[rr][2] = c.x; r[rr][3] = c.y;
            }
        }
        float4 wa = *(const float4*)(sw + ci * 12);
        float4 wb = *(const float4*)(sw + ci * 12 + 4);
        float4 wc = *(const float4*)(sw + ci * 12 + 8);
        float wv[9] = {wa.x, wa.y, wa.z, wa.w, wb.x, wb.y, wb.z, wb.w, wc.x};
#pragma unroll
        for (int t = 0; t < TX; t++) {
            accA[t] += wv[0]*r[0][t] + wv[2]*r[0][t+2] + wv[4]*r[1][t+1]
                     + wv[6]*r[2][t] + wv[8]*r[2][t+2];
            accB[t] += wv[1]*r[0][t+1] + wv[3]*r[1][t] + wv[5]*r[1][t+2]
                     + wv[7]*r[2][t+1];
        }
    }

    float thr = __ldg(thrp), leak = __ldg(leakp);
    long mbase = (((long)b * COUT + co) * S + y) * S + x0;
    long obase = (((long)b * COUT + co) * ROWS + (y + 1)) * RS + (x0 + 1);
#pragma unroll
    for (int t = 0; t < TX; t++)
        g_buf[out_off + obase + t] =
            lif_fire(&g_buf[mem_off + mbase + t], accA[t] + accB[t], thr, leak);
}

// ---------------- conv flavor W v2: NHWC, block per co, smem weights ------
template<int CIN, int CST, int S, int COUT, int NTHR>
__global__ __launch_bounds__(NTHR)
void k_conv_Wv2(int in_off, long wt_off, int mem_off, int out_off,
                const float* __restrict__ thrp, const float* __restrict__ leakp) {
    constexpr int SP = S + 2;
    constexpr int NWARP = NTHR / 32;
    __shared__ __align__(16) float sw[CIN * 9];
    int co = blockIdx.x;
    for (int i = threadIdx.x; i < CIN * 9; i += NTHR)
        sw[i] = __ldg(g_wt + wt_off + (long)co * CIN * 9 + i);
    __syncthreads();

    int warp = threadIdx.x >> 5, lane = threadIdx.x & 31;
    float thr = __ldg(thrp), leak = __ldg(leakp);

    for (int job = warp; job < BATCH * S; job += NWARP) {
        int y = job % S, b = job / S;
        float accA[S], accB[S];
#pragma unroll
        for (int t = 0; t < S; t++) { accA[t] = 0.f; accB[t] = 0.f; }

#pragma unroll
        for (int it = 0; it < CIN / 128; it++) {
            int cb = it * 128 + lane * 4;
#pragma unroll
            for (int rr = 0; rr < 3; rr++) {
                float4 w0 = *(const float4*)(sw + (rr * 3 + 0) * CIN + cb);
                float4 w1 = *(const float4*)(sw + (rr * 3 + 1) * CIN + cb);
                float4 w2 = *(const float4*)(sw + (rr * 3 + 2) * CIN + cb);
                const float* rp = g_buf + in_off + ((long)(b * SP + y + rr) * SP) * CST + cb;
#pragma unroll
                for (int j = 0; j < SP; j++) {
                    float4 a = __ldg((const float4*)(rp + j * CST));
                    if (j < S) {
                        accA[j]   += a.x * w0.x + a.z * w0.z;
                        accB[j]   += a.y * w0.y + a.w * w0.w;
                    }
                    if (j >= 1 && j - 1 < S) {
                        accA[j-1] += a.x * w1.x + a.z * w1.z;
                        accB[j-1] += a.y * w1.y + a.w * w1.w;
                    }
                    if (j >= 2) {
                        accA[j-2] += a.x * w2.x + a.z * w2.z;
                        accB[j-2] += a.y * w2.y + a.w * w2.w;
                    }
                }
            }
        }
#pragma unroll
        for (int t = 0; t < S; t++) {
            float v = accA[t] + accB[t];
#pragma unroll
            for (int o = 16; o; o >>= 1)
                v += __shfl_xor_sync(0xffffffffu, v, o);
            accA[t] = v;
        }
        if (lane == 0) {
#pragma unroll
            for (int t = 0; t < S; t++) {
                long midx = (((long)b * S + y) * S + t) * COUT + co;
                long oidx = (((long)b * SP + (y + 1)) * SP + (t + 1)) * (long)COUT + co;
                g_buf[out_off + oidx] =
                    lif_fire(&g_buf[mem_off + midx], accA[t], thr, leak);
            }
        }
    }
}

// ---------------- conv flavor W2 v2: 2x2 layers, block per co -------------
// 16 warps = (b, ci-group of 128); smem partial reduction across ci-groups.
__global__ __launch_bounds__(512)
void k_conv_W2v2(int in_off, long wt_off, int mem_off, int out_off,
                 const float* __restrict__ thrp, const float* __restrict__ leakp) {
    constexpr int CIN = 512, CST = 512, SP = 4, COUT = 512;
    __shared__ __align__(16) float sw[CIN * 9];
    __shared__ float spart[16][4];
    int co = blockIdx.x;
    for (int i = threadIdx.x; i < CIN * 9; i += 512)
        sw[i] = __ldg(g_wt + wt_off + (long)co * CIN * 9 + i);
    __syncthreads();

    int w = threadIdx.x >> 5, lane = threadIdx.x & 31;
    int b = w >> 2, cig = w & 3;
    int cb = cig * 128 + lane * 4;

    float4 wv[9];
#pragma unroll
    for (int t = 0; t < 9; t++)
        wv[t] = *(const float4*)(sw + t * CIN + cb);

    float aA[4] = {0.f, 0.f, 0.f, 0.f}, aB[4] = {0.f, 0.f, 0.f, 0.f};
#pragma unroll
    for (int iy = 0; iy < SP; iy++) {
        const float* rp = g_buf + in_off + ((long)(b * SP + iy) * SP) * CST + cb;
#pragma unroll
        for (int ix = 0; ix < SP; ix++) {
            float4 a = __ldg((const float4*)(rp + ix * CST));
#pragma unroll
            for (int oy = 0; oy < 2; oy++) {
                int dy = iy - oy;
                if (dy < 0 || dy > 2) continue;
#pragma unroll
                for (int ox = 0; ox < 2; ox++) {
                    int dx = ix - ox;
                    if (dx < 0 || dx > 2) continue;
                    float4 wt = wv[dy * 3 + dx];
                    int p = oy * 2 + ox;
                    aA[p] += a.x * wt.x + a.z * wt.z;
                    aB[p] += a.y * wt.y + a.w * wt.w;
                }
            }
        }
    }
#pragma unroll
    for (int p = 0; p < 4; p++) {
        float v = aA[p] + aB[p];
#pragma unroll
        for (int o = 16; o; o >>= 1)
            v += __shfl_xor_sync(0xffffffffu, v, o);
        if (lane == 0) spart[w][p] = v;
    }
    __syncthreads();

    if (threadIdx.x < 16) {
        int b2 = threadIdx.x >> 2, p = threadIdx.x & 3;
        float s = spart[b2 * 4 + 0][p] + spart[b2 * 4 + 1][p]
                + spart[b2 * 4 + 2][p] + spart[b2 * 4 + 3][p];
        int oy = p >> 1, ox = p & 1;
        float thr = __ldg(thrp), leak = __ldg(leakp);
        long midx = (((long)b2 * 2 + oy) * 2 + ox) * COUT + co;
        long oidx = (((long)b2 * SP + (oy + 1)) * SP + (ox + 1)) * (long)COUT + co;
        g_buf[out_off + oidx] =
            lif_fire(&g_buf[mem_off + midx], s, thr, leak);
    }
}

// ---------------- avg-pool 2x2 --------------------------------------------
template<int C, int S, int CI, int CO>   // NCHW(S) -> NCHW(S/2)
__global__ void k_pool_cc(int in_off, int out_off) {
    constexpr int SO = S / 2, RSI = S + 4, ROWSI = S + 2, RSO = SO + 4, ROWSO = SO + 2;
    int idx = blockIdx.x * blockDim.x + threadIdx.x;
    if (idx >= BATCH * C * SO * SO) return;
    int x = idx % SO, y = (idx / SO) % SO;
    int c = (idx / (SO * SO)) % C, b = idx / (SO * SO * C);
    const float* p = g_buf + in_off + ((long)(b * CI + c) * ROWSI + 2 * y + 1) * RSI + 2 * x + 1;
    float v = 0.25f * (p[0] + p[1] + p[RSI] + p[RSI + 1]);
    g_buf[out_off + ((long)(b * CO + c) * ROWSO + y + 1) * RSO + x + 1] = v;
}

template<int C, int S, int CI, int CSTO>  // NCHW(S) -> NHWC(S/2)
__global__ void k_pool_cn(int in_off, int out_off) {
    constexpr int SO = S / 2, RSI = S + 4, ROWSI = S + 2, SPO = SO + 2;
    int idx = blockIdx.x * blockDim.x + threadIdx.x;
    if (idx >= BATCH * C * SO * SO) return;
    int c = idx % C;
    int x = (idx / C) % SO, y = (idx / (C * SO)) % SO, b = idx / (C * SO * SO);
    const float* p = g_buf + in_off + ((long)(b * CI + c) * ROWSI + 2 * y + 1) * RSI + 2 * x + 1;
    float v = 0.25f * (p[0] + p[1] + p[RSI] + p[RSI + 1]);
    g_buf[out_off + (((long)b * SPO + y + 1) * SPO + x + 1) * CSTO + c] = v;
}

template<int C, int S, int CSTI, int CSTO>  // NHWC(S) -> NHWC(S/2)
__global__ void k_pool_nn(int in_off, int out_off) {
    constexpr int SO = S / 2, SPI = S + 2, SPO = SO + 2;
    int idx = blockIdx.x * blockDim.x + threadIdx.x;
    if (idx >= BATCH * C * SO * SO) return;
    int c = idx % C;
    int x = (idx / C) % SO, y = (idx / (C * SO)) % SO, b = idx / (C * SO * SO);
    const float* p = g_buf + in_off + (((long)b * SPI + 2 * y + 1) * SPI + 2 * x + 1) * CSTI + c;
    float v = 0.25f * (p[0] + p[CSTI] + p[(long)SPI * CSTI] + p[(long)(SPI + 1) * CSTI]);
    g_buf[out_off + (((long)b * SPO + y + 1) * SPO + x + 1) * CSTO + c] = v;
}

// ---------------- fully connected: warp per output, 4 batches fused -------
__global__ __launch_bounds__(256)
void k_fc0(const float* __restrict__ W, int mem_off, int out_off,
           const float* __restrict__ thrp, const float* __restrict__ leakp) {
    int gt = blockIdx.x * blockDim.x + threadIdx.x;
    int o = gt >> 5, lane = gt & 31;
    if (o >= 4096) return;
    const float* src = g_buf + OFF_2B;
    float acc[4] = {0.f, 0.f, 0.f, 0.f};
    for (int c = lane; c < 512; c += 32) {
        float4 wv = __ldg((const float4*)(W + (long)o * 2048 + c * 4));
#pragma unroll
        for (int b = 0; b < 4; b++) {
            long base = ((long)(b * 16 + 5)) * 512 + c;
            float a00 = src[base], a01 = src[base + 512];
            float a10 = src[base + 4 * 512], a11 = src[base + 5 * 512];
            acc[b] += wv.x * a00 + wv.y * a01 + wv.z * a10 + wv.w * a11;
        }
    }
#pragma unroll
    for (int b = 0; b < 4; b++)
#pragma unroll
        for (int of = 16; of; of >>= 1)
            acc[b] += __shfl_xor_sync(0xffffffffu, acc[b], of);
    if (lane == 0) {
        float thr = __ldg(thrp), leak = __ldg(leakp);
#pragma unroll
        for (int b = 0; b < 4; b++)
            g_buf[out_off + (long)b * 4096 + o] =
                lif_fire(&g_buf[mem_off + (long)b * 4096 + o], acc[b], thr, leak);
    }
}

template<int KD>
__global__ __launch_bounds__(256)
void k_fc4(const float* __restrict__ W, int in_off, int mem_off, int out_off,
           const float* __restrict__ thrp, const float* __restrict__ leakp,
           int OUTN) {
    int gt = blockIdx.x * blockDim.x + threadIdx.x;
    int o = gt >> 5, lane = gt & 31;
    if (o >= OUTN) return;
    const float4* wp = (const float4*)(W + (long)o * KD);
    const float4* ip = (const float4*)(g_buf + in_off);
    float acc[4] = {0.f, 0.f, 0.f, 0.f};
    for (int k = lane; k < KD / 4; k += 32) {
        float4 wv = __ldg(wp + k);
#pragma unroll
        for (int b = 0; b < 4; b++) {
            float4 a = ip[b * (KD / 4) + k];
            acc[b] += wv.x * a.x + wv.y * a.y + wv.z * a.z + wv.w * a.w;
        }
    }
#pragma unroll
    for (int b = 0; b < 4; b++)
#pragma unroll
        for (int of = 16; of; of >>= 1)
            acc[b] += __shfl_xor_sync(0xffffffffu, acc[b], of);
    if (lane == 0) {
        float thr = __ldg(thrp), leak = __ldg(leakp);
#pragma unroll
        for (int b = 0; b < 4; b++)
            g_buf[out_off + (long)b * OUTN + o] =
                lif_fire(&g_buf[mem_off + (long)b * OUTN + o], acc[b], thr, leak);
    }
}

__global__ void k_logits4(const float* __restrict__ W, int in_off,
                          float* __restrict__ dout) {
    int gt = blockIdx.x * blockDim.x + threadIdx.x;
    int o = gt >> 5, lane = gt & 31;
    if (o >= 10) return;
    const float4* wp = (const float4*)(W + (long)o * 4096);
    const float4* ip = (const float4*)(g_buf + in_off);
    float acc[4] = {0.f, 0.f, 0.f, 0.f};
    for (int k = lane; k < 1024; k += 32) {
        float4 wv = __ldg(wp + k);
#pragma unroll
        for (int b = 0; b < 4; b++) {
            float4 a = ip[b * 1024 + k];
            acc[b] += wv.x * a.x + wv.y * a.y + wv.z * a.z + wv.w * a.w;
        }
    }
#pragma unroll
    for (int b = 0; b < 4; b++)
#pragma unroll
        for (int of = 16; of; of >>= 1)
            acc[b] += __shfl_xor_sync(0xffffffffu, acc[b], of);
    if (lane == 0)
#pragma unroll
        for (int b = 0; b < 4; b++)
            dout[b * 10 + o] += acc[b];
}

// ---------------- launch --------------------------------------------------
static inline int gup(long n, int b) { return (int)((n + b - 1) / b); }

extern "C" void kernel_launch(void* const* d_in, const int* in_sizes, int n_in,
                              void* d_out, int out_size) {
    const float* x = (const float*)d_in[0];
    const float* w[13];
    for (int i = 0; i < 13; i++) w[i] = (const float*)d_in[1 + i];
    const float* fc0w = (const float*)d_in[14];
    const float* fc1w = (const float*)d_in[15];
    const float* fc2w = (const float*)d_in[16];
    const float* thr  = (const float*)d_in[17];
    const float* leak = (const float*)d_in[18];
    float* out = (float*)d_out;

    k_zero<<<gup(TOTAL_BUF, 256), 256>>>(out);
    k_pad_x<<<gup(BATCH * 3 * 1024, 256), 256>>>(x);

    WP wp;
    for (int i = 0; i < 9; i++) wp.p[i] = w[4 + i];
    k_wtrans_all<<<dim3(512, 9), 256>>>(wp);

    for (int t = 0; t < 3; t++) {
        // ---- 32x32, NCHW, TX=4 ----
        k_conv_T<3, 3, 32, 64, 4, 4><<<64 * 4, 256>>>(
            OFF_X, w[0], M0, OFF_32A, thr + 0, leak + 0);
        k_conv_T<64, 64, 32, 64, 4, 4><<<64 * 4, 256>>>(
            OFF_32A, w[1], M1, OFF_32B, thr + 1, leak + 1);
        k_pool_cc<64, 32, 64, 128><<<gup(4L * 64 * 16 * 16, 256), 256>>>(OFF_32B, OFF_16A);

        // ---- 16x16, NCHW, TX=2 (2x the warps of TX=4) ----
        k_conv_T<64, 128, 16, 128, 2, 2><<<128 * 2, 256>>>(
            OFF_16A, w[2], M2, OFF_16B, thr + 2, leak + 2);
        k_conv_T<128, 128, 16, 128, 2, 2><<<128 * 2, 256>>>(
            OFF_16B, w[3], M3, OFF_16A, thr + 3, leak + 3);
        k_pool_cn<128, 16, 128, 256><<<gup(4L * 128 * 8 * 8, 256), 256>>>(OFF_16A, OFF_8A);

        // ---- 8x8, NHWC, block-per-co + smem weights ----
        k_conv_Wv2<128, 256, 8, 256, 512><<<256, 512>>>(
            OFF_8A, WT4, M4, OFF_8B, thr + 4, leak + 4);
        k_conv_Wv2<256, 256, 8, 256, 512><<<256, 512>>>(
            OFF_8B, WT5, M5, OFF_8A, thr + 5, leak + 5);
        k_conv_Wv2<256, 256, 8, 256, 512><<<256, 512>>>(
            OFF_8A, WT6, M6, OFF_8B, thr + 6, leak + 6);
        k_pool_nn<256, 8, 256, 512><<<gup(4L * 256 * 4 * 4, 256), 256>>>(OFF_8B, OFF_4A);

        // ---- 4x4, NHWC ----
        k_conv_Wv2<256, 512, 4, 512, 256><<<512, 256>>>(
            OFF_4A, WT7, M7, OFF_4B, thr + 7, leak + 7);
        k_conv_Wv2<512, 512, 4, 512, 256><<<512, 256>>>(
            OFF_4B, WT8, M8, OFF_4A, thr + 8, leak + 8);
        k_conv_Wv2<512, 512, 4, 512, 256><<<512, 256>>>(
            OFF_4A, WT9, M9, OFF_4B, thr + 9, leak + 9);
        k_pool_nn<512, 4, 512, 512><<<gup(4L * 512 * 2 * 2, 256), 256>>>(OFF_4B, OFF_2A);

        // ---- 2x2, NHWC, block-per-co, ci-split warps ----
        k_conv_W2v2<<<512, 512>>>(OFF_2A, WT10, M10, OFF_2B, thr + 10, leak + 10);
        k_conv_W2v2<<<512, 512>>>(OFF_2B, WT11, M11, OFF_2A, thr + 11, leak + 11);
        k_conv_W2v2<<<512, 512>>>(OFF_2A, WT12, M12, OFF_2B, thr + 12, leak + 12);

        // ---- classifier ----
        k_fc0<<<gup(4096L * 32, 256), 256>>>(fc0w, MF0, OFF_FCS0, thr + 13, leak + 13);
        k_fc4<4096><<<gup(4096L * 32, 256), 256>>>(
            fc1w, OFF_FCS0, MF1, OFF_FCS1, thr + 14, leak + 14, 4096);
        k_logits4<<<2, 256>>>(fc2w, OFF_FCS1, out);
    }
}

// round 10
// speedup vs baseline: 1.4477x; 1.4477x over previous
#include <cuda_runtime.h>
#include <cuda_bf16.h>

#define DEV_INLINE __device__ __forceinline__
constexpr int BATCH = 4;

// ---------------- buffer layout (floats) ----------------------------------
// NCHW padded: rows S+2, row-stride S+4. NHWC padded: [B][S+2][S+2][CST].
constexpr int OFF_X    = 0;                         // [4][3][34][36]
constexpr int SZ_X     = BATCH * 3 * 34 * 36;
constexpr int OFF_32A  = OFF_X + SZ_X;              // cap 64
constexpr int SZ_32    = BATCH * 64 * 34 * 36;
constexpr int OFF_32B  = OFF_32A + SZ_32;
constexpr int OFF_16A  = OFF_32B + SZ_32;           // cap 128
constexpr int SZ_16    = BATCH * 128 * 18 * 20;
constexpr int OFF_16B  = OFF_16A + SZ_16;
constexpr int OFF_8A   = OFF_16B + SZ_16;           // NHWC [4][10][10][256]
constexpr int SZ_8     = BATCH * 10 * 10 * 256;
constexpr int OFF_8B   = OFF_8A + SZ_8;
constexpr int OFF_4A   = OFF_8B + SZ_8;             // NHWC [4][6][6][512]
constexpr int SZ_4     = BATCH * 6 * 6 * 512;
constexpr int OFF_4B   = OFF_4A + SZ_4;
constexpr int OFF_2A   = OFF_4B + SZ_4;             // NHWC [4][4][4][512]
constexpr int SZ_2     = BATCH * 4 * 4 * 512;
constexpr int OFF_2B   = OFF_2A + SZ_2;
constexpr int OFF_FCS0 = OFF_2B + SZ_2;             // [4][4096]
constexpr int OFF_FCS1 = OFF_FCS0 + BATCH * 4096;

constexpr int M0  = OFF_FCS1 + BATCH * 4096;
constexpr int M1  = M0  + BATCH * 64  * 32 * 32;
constexpr int M2  = M1  + BATCH * 64  * 32 * 32;
constexpr int M3  = M2  + BATCH * 128 * 16 * 16;
constexpr int M4  = M3  + BATCH * 128 * 16 * 16;
constexpr int M5  = M4  + BATCH * 256 * 8 * 8;
constexpr int M6  = M5  + BATCH * 256 * 8 * 8;
constexpr int M7  = M6  + BATCH * 256 * 8 * 8;
constexpr int M8  = M7  + BATCH * 512 * 4 * 4;
constexpr int M9  = M8  + BATCH * 512 * 4 * 4;
constexpr int M10 = M9  + BATCH * 512 * 4 * 4;
constexpr int M11 = M10 + BATCH * 512 * 2 * 2;
constexpr int M12 = M11 + BATCH * 512 * 2 * 2;
constexpr int MF0 = M12 + BATCH * 512 * 2 * 2;
constexpr int MF1 = MF0 + BATCH * 4096;
constexpr int TOTAL_BUF = MF1 + BATCH * 4096;

__device__ __align__(16) float g_buf[TOTAL_BUF];

// transposed weights [co][tap][ci] for conv layers 4..12
constexpr long WT4  = 0;
constexpr long WT5  = WT4  + 256L * 128 * 9;
constexpr long WT6  = WT5  + 256L * 256 * 9;
constexpr long WT7  = WT6  + 256L * 256 * 9;
constexpr long WT8  = WT7  + 512L * 256 * 9;
constexpr long WT9  = WT8  + 512L * 512 * 9;
constexpr long WT10 = WT9  + 512L * 512 * 9;
constexpr long WT11 = WT10 + 512L * 512 * 9;
constexpr long WT12 = WT11 + 512L * 512 * 9;
constexpr long WT_TOTAL = WT12 + 512L * 512 * 9;
__device__ __align__(16) float g_wt[WT_TOTAL];

// ---------------- multi-compartment LIF (K=2), exact ----------------------
DEV_INLINE float lif_fire(float* memp, float syn, float thr, float leak) {
    float m = leak * (*memp) + syn;
    float e0 = m / thr          - 1.0f;
    float o0 = 1.0f - m / (2.0f * thr);
    float e1 = m / (2.0f * thr) - 1.0f;
    float o1 = 1.0f - m / (4.0f * thr);
    float v = 0.0f;
    if (e0 > 0.0f && o0 >= 0.0f) v = 1.0f;
    if (e1 > 0.0f && o1 >= 0.0f) v = 2.0f;
    *memp = m - thr * v;
    return v;
}

// ---------------- housekeeping --------------------------------------------
__global__ void k_zero(float* __restrict__ dout) {
    int i = blockIdx.x * blockDim.x + threadIdx.x;
    if (i < TOTAL_BUF) g_buf[i] = 0.0f;
    if (i < BATCH * 10) dout[i] = 0.0f;
}

__global__ void k_pad_x(const float* __restrict__ x) {
    int idx = blockIdx.x * blockDim.x + threadIdx.x;
    if (idx >= BATCH * 3 * 32 * 32) return;
    int xx = idx & 31;
    int y  = (idx >> 5) & 31;
    int c  = (idx >> 10) % 3;
    int b  = idx / (3 * 1024);
    g_buf[OFF_X + ((b * 3 + c) * 34 + (y + 1)) * 36 + (xx + 1)] = x[idx];
}

struct WP { const float* p[9]; };
__global__ void k_wtrans_all(WP wp) {
    __shared__ float s[4608];
    const int CINs[9]  = {128, 256, 256, 256, 512, 512, 512, 512, 512};
    const int COUTs[9] = {256, 256, 256, 512, 512, 512, 512, 512, 512};
    const long OFFs[9] = {WT4, WT5, WT6, WT7, WT8, WT9, WT10, WT11, WT12};
    int l  = blockIdx.y;
    int co = blockIdx.x;
    int CIN = CINs[l];
    if (co >= COUTs[l]) return;
    const float* src = wp.p[l] + (long)co * CIN * 9;
    float* dst = g_wt + OFFs[l] + (long)co * CIN * 9;
    int n = CIN * 9;
    for (int i = threadIdx.x; i < n; i += 256) s[i] = src[i];
    __syncthreads();
    for (int i = threadIdx.x; i < n; i += 256) {
        int ci = i % CIN, t = i / CIN;
        dst[i] = s[ci * 9 + t];
    }
}

// ---------------- conv flavor T: NCHW, block per (co,part), smem weights --
template<int CIN, int CICAP, int S, int COUT, int PARTS, int TX>
__global__ __launch_bounds__(256)
void k_conv_T(int in_off, const float* __restrict__ w, int mem_off, int out_off,
              const float* __restrict__ thrp, const float* __restrict__ leakp) {
    constexpr int RS = S + 4, ROWS = S + 2, NX = S / TX;
    constexpr int PLANE = ROWS * RS;
    constexpr int P = BATCH * S * NX;
    constexpr int TPJ = P / PARTS;
    static_assert(TPJ == 256, "block must exactly cover its partition");
    __shared__ __align__(16) float sw[CIN * 12];
    int co   = blockIdx.x / PARTS;
    int part = blockIdx.x % PARTS;
    for (int i = threadIdx.x; i < CIN * 9; i += 256)
        sw[(i / 9) * 12 + (i % 9)] = __ldg(w + (long)co * CIN * 9 + i);
    __syncthreads();

    int tid = part * TPJ + threadIdx.x;
    int x0 = (tid % NX) * TX;
    int y  = (tid / NX) % S;
    int b  = tid / (NX * S);

    const float* ip = g_buf + in_off + (long)b * CICAP * PLANE + y * RS + x0;
    float accA[TX], accB[TX];
#pragma unroll
    for (int t = 0; t < TX; t++) { accA[t] = 0.f; accB[t] = 0.f; }

    for (int ci = 0; ci < CIN; ci++) {
        const float* p = ip + ci * PLANE;
        float r[3][TX + 2];
#pragma unroll
        for (int rr = 0; rr < 3; rr++) {
            if constexpr (TX == 4) {
                float4 a = __ldg((const float4*)(p + rr * RS));
                float4 c = __ldg((const float4*)(p + rr * RS + 4));
                r[rr][0] = a.x; r[rr][1] = a.y; r[rr][2] = a.z; r[rr][3] = a.w;
                r[rr][4] = c.x; r[rr][5] = c.y;
            } else {
                float2 a = __ldg((const float2*)(p + rr * RS));
                float2 c = __ldg((const float2*)(p + rr * RS + 2));
                r[rr][0] = a.x; r[rr][1] = a.y; r[rr][2] = c.x; r[rr][3] = c.y;
            }
        }
        float4 wa = *(const float4*)(sw + ci * 12);
        float4 wb = *(const float4*)(sw + ci * 12 + 4);
        float4 wc = *(const float4*)(sw + ci * 12 + 8);
        float wv[9] = {wa.x, wa.y, wa.z, wa.w, wb.x, wb.y, wb.z, wb.w, wc.x};
#pragma unroll
        for (int t = 0; t < TX; t++) {
            accA[t] += wv[0]*r[0][t] + wv[2]*r[0][t+2] + wv[4]*r[1][t+1]
                     + wv[6]*r[2][t] + wv[8]*r[2][t+2];
            accB[t] += wv[1]*r[0][t+1] + wv[3]*r[1][t] + wv[5]*r[1][t+2]
                     + wv[7]*r[2][t+1];
        }
    }

    float thr = __ldg(thrp), leak = __ldg(leakp);
    long mbase = (((long)b * COUT + co) * S + y) * S + x0;
    long obase = (((long)b * COUT + co) * ROWS + (y + 1)) * RS + (x0 + 1);
#pragma unroll
    for (int t = 0; t < TX; t++)
        g_buf[out_off + obase + t] =
            lif_fire(&g_buf[mem_off + mbase + t], accA[t] + accB[t], thr, leak);
}

// ---------------- conv flavor G: NHWC, warp = (b, y), G co's per warp -----
// Weights for a co-group staged in smem in 128-channel chunks.
// Lane owns 4 channels of the current chunk. acc[G][S] per thread; butterfly
// reduce; lanes 0..G*S-1 each write one output.
template<int CIN, int CST, int S, int COUT, int G, int WPB, int PARTS>
__global__ __launch_bounds__(WPB * 32)
void k_conv_G(int in_off, long wt_off, int mem_off, int out_off,
              const float* __restrict__ thrp, const float* __restrict__ leakp) {
    constexpr int SP = S + 2;
    constexpr int NTHR = WPB * 32;
    constexpr int CHUNKS = CIN / 128;
    static_assert(WPB * PARTS == BATCH * S, "warps must exactly cover jobs");
    static_assert(G * S <= 32, "one lane per output");
    __shared__ __align__(16) float sw[G * 9 * 128];

    int cog  = blockIdx.x / PARTS;
    int part = blockIdx.x % PARTS;
    int warp = threadIdx.x >> 5, lane = threadIdx.x & 31;
    int job  = part * WPB + warp;
    int b = job / S, y = job % S;

    float acc[G][S];
#pragma unroll
    for (int g = 0; g < G; g++)
#pragma unroll
        for (int x = 0; x < S; x++) acc[g][x] = 0.f;

    int cb = lane * 4;
    for (int ch = 0; ch < CHUNKS; ch++) {
        __syncthreads();
        const float* wsrc = g_wt + wt_off + ((long)cog * G) * CIN * 9 + ch * 128;
        for (int i = threadIdx.x; i < G * 9 * 32; i += NTHR) {
            int g = i / (9 * 32);
            int r = i % (9 * 32);
            int t = r / 32, c4 = r % 32;
            *(float4*)(sw + (g * 9 + t) * 128 + c4 * 4) =
                __ldg((const float4*)(wsrc + ((long)g * 9 + t) * CIN + c4 * 4));
        }
        __syncthreads();

        const float* base = g_buf + in_off + ch * 128 + cb;
#pragma unroll
        for (int rr = 0; rr < 3; rr++) {
            const float* rp = base + ((long)(b * SP + y + rr) * SP) * CST;
            float4 a[S + 2];
#pragma unroll
            for (int j = 0; j < S + 2; j++)
                a[j] = __ldg((const float4*)(rp + (long)j * CST));
#pragma unroll
            for (int g = 0; g < G; g++) {
                const float* wrow = sw + (g * 9 + rr * 3) * 128 + cb;
                float4 w0 = *(const float4*)(wrow);
                float4 w1 = *(const float4*)(wrow + 128);
                float4 w2 = *(const float4*)(wrow + 256);
#pragma unroll
                for (int x = 0; x < S; x++) {
                    float4 a0 = a[x], a1 = a[x + 1], a2 = a[x + 2];
                    acc[g][x] += a0.x*w0.x + a0.y*w0.y + a0.z*w0.z + a0.w*w0.w
                               + a1.x*w1.x + a1.y*w1.y + a1.z*w1.z + a1.w*w1.w
                               + a2.x*w2.x + a2.y*w2.y + a2.z*w2.z + a2.w*w2.w;
                }
            }
        }
    }

    float mine = 0.f;
#pragma unroll
    for (int g = 0; g < G; g++)
#pragma unroll
        for (int x = 0; x < S; x++) {
            float v = acc[g][x];
#pragma unroll
            for (int o = 16; o; o >>= 1)
                v += __shfl_xor_sync(0xffffffffu, v, o);
            if (lane == g * S + x) mine = v;
        }

    if (lane < G * S) {
        int g = lane / S, x = lane % S;
        int co = cog * G + g;
        float thr = __ldg(thrp), leak = __ldg(leakp);
        long midx = (((long)b * S + y) * S + x) * COUT + co;
        long oidx = (((long)b * SP + (y + 1)) * SP + (x + 1)) * (long)COUT + co;
        g_buf[out_off + oidx] =
            lif_fire(&g_buf[mem_off + midx], mine, thr, leak);
    }
}

// ---------------- avg-pool 2x2 --------------------------------------------
template<int C, int S, int CI, int CO>   // NCHW(S) -> NCHW(S/2)
__global__ void k_pool_cc(int in_off, int out_off) {
    constexpr int SO = S / 2, RSI = S + 4, ROWSI = S + 2, RSO = SO + 4, ROWSO = SO + 2;
    int idx = blockIdx.x * blockDim.x + threadIdx.x;
    if (idx >= BATCH * C * SO * SO) return;
    int x = idx % SO, y = (idx / SO) % SO;
    int c = (idx / (SO * SO)) % C, b = idx / (SO * SO * C);
    const float* p = g_buf + in_off + ((long)(b * CI + c) * ROWSI + 2 * y + 1) * RSI + 2 * x + 1;
    float v = 0.25f * (p[0] + p[1] + p[RSI] + p[RSI + 1]);
    g_buf[out_off + ((long)(b * CO + c) * ROWSO + y + 1) * RSO + x + 1] = v;
}

template<int C, int S, int CI, int CSTO>  // NCHW(S) -> NHWC(S/2)
__global__ void k_pool_cn(int in_off, int out_off) {
    constexpr int SO = S / 2, RSI = S + 4, ROWSI = S + 2, SPO = SO + 2;
    int idx = blockIdx.x * blockDim.x + threadIdx.x;
    if (idx >= BATCH * C * SO * SO) return;
    int c = idx % C;
    int x = (idx / C) % SO, y = (idx / (C * SO)) % SO, b = idx / (C * SO * SO);
    const float* p = g_buf + in_off + ((long)(b * CI + c) * ROWSI + 2 * y + 1) * RSI + 2 * x + 1;
    float v = 0.25f * (p[0] + p[1] + p[RSI] + p[RSI + 1]);
    g_buf[out_off + (((long)b * SPO + y + 1) * SPO + x + 1) * CSTO + c] = v;
}

template<int C, int S, int CSTI, int CSTO>  // NHWC(S) -> NHWC(S/2)
__global__ void k_pool_nn(int in_off, int out_off) {
    constexpr int SO = S / 2, SPI = S + 2, SPO = SO + 2;
    int idx = blockIdx.x * blockDim.x + threadIdx.x;
    if (idx >= BATCH * C * SO * SO) return;
    int c = idx % C;
    int x = (idx / C) % SO, y = (idx / (C * SO)) % SO, b = idx / (C * SO * SO);
    const float* p = g_buf + in_off + (((long)b * SPI + 2 * y + 1) * SPI + 2 * x + 1) * CSTI + c;
    float v = 0.25f * (p[0] + p[CSTI] + p[(long)SPI * CSTI] + p[(long)(SPI + 1) * CSTI]);
    g_buf[out_off + (((long)b * SPO + y + 1) * SPO + x + 1) * CSTO + c] = v;
}

// ---------------- fully connected: warp per output, 4 batches fused -------
__global__ __launch_bounds__(256)
void k_fc0(const float* __restrict__ W, int mem_off, int out_off,
           const float* __restrict__ thrp, const float* __restrict__ leakp) {
    int gt = blockIdx.x * blockDim.x + threadIdx.x;
    int o = gt >> 5, lane = gt & 31;
    if (o >= 4096) return;
    const float* src = g_buf + OFF_2B;
    float acc[4] = {0.f, 0.f, 0.f, 0.f};
    for (int c = lane; c < 512; c += 32) {
        float4 wv = __ldg((const float4*)(W + (long)o * 2048 + c * 4));
#pragma unroll
        for (int b = 0; b < 4; b++) {
            long base = ((long)(b * 16 + 5)) * 512 + c;
            float a00 = src[base], a01 = src[base + 512];
            float a10 = src[base + 4 * 512], a11 = src[base + 5 * 512];
            acc[b] += wv.x * a00 + wv.y * a01 + wv.z * a10 + wv.w * a11;
        }
    }
#pragma unroll
    for (int b = 0; b < 4; b++)
#pragma unroll
        for (int of = 16; of; of >>= 1)
            acc[b] += __shfl_xor_sync(0xffffffffu, acc[b], of);
    if (lane == 0) {
        float thr = __ldg(thrp), leak = __ldg(leakp);
#pragma unroll
        for (int b = 0; b < 4; b++)
            g_buf[out_off + (long)b * 4096 + o] =
                lif_fire(&g_buf[mem_off + (long)b * 4096 + o], acc[b], thr, leak);
    }
}

template<int KD>
__global__ __launch_bounds__(256)
void k_fc4(const float* __restrict__ W, int in_off, int mem_off, int out_off,
           const float* __restrict__ thrp, const float* __restrict__ leakp,
           int OUTN) {
    int gt = blockIdx.x * blockDim.x + threadIdx.x;
    int o = gt >> 5, lane = gt & 31;
    if (o >= OUTN) return;
    const float4* wp = (const float4*)(W + (long)o * KD);
    const float4* ip = (const float4*)(g_buf + in_off);
    float acc[4] = {0.f, 0.f, 0.f, 0.f};
    for (int k = lane; k < KD / 4; k += 32) {
        float4 wv = __ldg(wp + k);
#pragma unroll
        for (int b = 0; b < 4; b++) {
            float4 a = ip[b * (KD / 4) + k];
            acc[b] += wv.x * a.x + wv.y * a.y + wv.z * a.z + wv.w * a.w;
        }
    }
#pragma unroll
    for (int b = 0; b < 4; b++)
#pragma unroll
        for (int of = 16; of; of >>= 1)
            acc[b] += __shfl_xor_sync(0xffffffffu, acc[b], of);
    if (lane == 0) {
        float thr = __ldg(thrp), leak = __ldg(leakp);
#pragma unroll
        for (int b = 0; b < 4; b++)
            g_buf[out_off + (long)b * OUTN + o] =
                lif_fire(&g_buf[mem_off + (long)b * OUTN + o], acc[b], thr, leak);
    }
}

__global__ void k_logits4(const float* __restrict__ W, int in_off,
                          float* __restrict__ dout) {
    int gt = blockIdx.x * blockDim.x + threadIdx.x;
    int o = gt >> 5, lane = gt & 31;
    if (o >= 10) return;
    const float4* wp = (const float4*)(W + (long)o * 4096);
    const float4* ip = (const float4*)(g_buf + in_off);
    float acc[4] = {0.f, 0.f, 0.f, 0.f};
    for (int k = lane; k < 1024; k += 32) {
        float4 wv = __ldg(wp + k);
#pragma unroll
        for (int b = 0; b < 4; b++) {
            float4 a = ip[b * 1024 + k];
            acc[b] += wv.x * a.x + wv.y * a.y + wv.z * a.z + wv.w * a.w;
        }
    }
#pragma unroll
    for (int b = 0; b < 4; b++)
#pragma unroll
        for (int of = 16; of; of >>= 1)
            acc[b] += __shfl_xor_sync(0xffffffffu, acc[b], of);
    if (lane == 0)
#pragma unroll
        for (int b = 0; b < 4; b++)
            dout[b * 10 + o] += acc[b];
}

// ---------------- launch --------------------------------------------------
static inline int gup(long n, int b) { return (int)((n + b - 1) / b); }

extern "C" void kernel_launch(void* const* d_in, const int* in_sizes, int n_in,
                              void* d_out, int out_size) {
    const float* x = (const float*)d_in[0];
    const float* w[13];
    for (int i = 0; i < 13; i++) w[i] = (const float*)d_in[1 + i];
    const float* fc0w = (const float*)d_in[14];
    const float* fc1w = (const float*)d_in[15];
    const float* fc2w = (const float*)d_in[16];
    const float* thr  = (const float*)d_in[17];
    const float* leak = (const float*)d_in[18];
    float* out = (float*)d_out;

    k_zero<<<gup(TOTAL_BUF, 256), 256>>>(out);
    k_pad_x<<<gup(BATCH * 3 * 1024, 256), 256>>>(x);

    WP wp;
    for (int i = 0; i < 9; i++) wp.p[i] = w[4 + i];
    k_wtrans_all<<<dim3(512, 9), 256>>>(wp);

    for (int t = 0; t < 3; t++) {
        // ---- 32x32, NCHW, TX=4 ----
        k_conv_T<3, 3, 32, 64, 4, 4><<<64 * 4, 256>>>(
            OFF_X, w[0], M0, OFF_32A, thr + 0, leak + 0);
        k_conv_T<64, 64, 32, 64, 4, 4><<<64 * 4, 256>>>(
            OFF_32A, w[1], M1, OFF_32B, thr + 1, leak + 1);
        k_pool_cc<64, 32, 64, 128><<<gup(4L * 64 * 16 * 16, 256), 256>>>(OFF_32B, OFF_16A);

        // ---- 16x16, NCHW, TX=2 ----
        k_conv_T<64, 128, 16, 128, 2, 2><<<128 * 2, 256>>>(
            OFF_16A, w[2], M2, OFF_16B, thr + 2, leak + 2);
        k_conv_T<128, 128, 16, 128, 2, 2><<<128 * 2, 256>>>(
            OFF_16B, w[3], M3, OFF_16A, thr + 3, leak + 3);
        k_pool_cn<128, 16, 128, 256><<<gup(4L * 128 * 8 * 8, 256), 256>>>(OFF_16A, OFF_8A);

        // ---- 8x8, NHWC, co-blocked (G=4) ----
        k_conv_G<128, 256, 8, 256, 4, 8, 4><<<(256 / 4) * 4, 256>>>(
            OFF_8A, WT4, M4, OFF_8B, thr + 4, leak + 4);
        k_conv_G<256, 256, 8, 256, 4, 8, 4><<<(256 / 4) * 4, 256>>>(
            OFF_8B, WT5, M5, OFF_8A, thr + 5, leak + 5);
        k_conv_G<256, 256, 8, 256, 4, 8, 4><<<(256 / 4) * 4, 256>>>(
            OFF_8A, WT6, M6, OFF_8B, thr + 6, leak + 6);
        k_pool_nn<256, 8, 256, 512><<<gup(4L * 256 * 4 * 4, 256), 256>>>(OFF_8B, OFF_4A);

        // ---- 4x4, NHWC, co-blocked (G=8) ----
        k_conv_G<256, 512, 4, 512, 8, 8, 2><<<(512 / 8) * 2, 256>>>(
            OFF_4A, WT7, M7, OFF_4B, thr + 7, leak + 7);
        k_conv_G<512, 512, 4, 512, 8, 8, 2><<<(512 / 8) * 2, 256>>>(
            OFF_4B, WT8, M8, OFF_4A, thr + 8, leak + 8);
        k_conv_G<512, 512, 4, 512, 8, 8, 2><<<(512 / 8) * 2, 256>>>(
            OFF_4A, WT9, M9, OFF_4B, thr + 9, leak + 9);
        k_pool_nn<512, 4, 512, 512><<<gup(4L * 512 * 2 * 2, 256), 256>>>(OFF_4B, OFF_2A);

        // ---- 2x2, NHWC, co-blocked (G=4) ----
        k_conv_G<512, 512, 2, 512, 4, 8, 1><<<(512 / 4) * 1, 256>>>(
            OFF_2A, WT10, M10, OFF_2B, thr + 10, leak + 10);
        k_conv_G<512, 512, 2, 512, 4, 8, 1><<<(512 / 4) * 1, 256>>>(
            OFF_2B, WT11, M11, OFF_2A, thr + 11, leak + 11);
        k_conv_G<512, 512, 2, 512, 4, 8, 1><<<(512 / 4) * 1, 256>>>(
            OFF_2A, WT12, M12, OFF_2B, thr + 12, leak + 12);

        // ---- classifier ----
        k_fc0<<<gup(4096L * 32, 256), 256>>>(fc0w, MF0, OFF_FCS0, thr + 13, leak + 13);
        k_fc4<4096><<<gup(4096L * 32, 256), 256>>>(
            fc1w, OFF_FCS0, MF1, OFF_FCS1, thr + 14, leak + 14, 4096);
        k_logits4<<<2, 256>>>(fc2w, OFF_FCS1, out);
    }
}